// round 1
// baseline (speedup 1.0000x reference)
#include <cuda_runtime.h>
#include <math.h>

// ---------------------------------------------------------------------------
// SpikeAttention (linear attention, ELU+1 feature map)
//   B=4, N=4096, DIM=1024, HEADS=16, HEAD_DIM=64
// Pipeline:
//   1) Q = elu(x@Wq^T + bq)+1   (GEMM, act=1)
//   2) K = elu(x@Wk^T + bk)+1   (GEMM, act=1)
//   3) V = x@Wv^T + bv          (GEMM, act=0)
//   4) KV[b,h,d,v] = sum_n K*V ; Ksum[b,h,d] = sum_n K   (split-n + atomics)
//   5) attn[b,n,h,v] = (Q@KV) / (Q@Ksum + 1e-6) * sigmoid(stdp[h])
//   6) out = attn@Wo^T + bo     (GEMM, act=0)
//   7) tail: out2 = stdp (stop_gradient)
// ---------------------------------------------------------------------------

#define BDIM  4
#define NSEQ  4096
#define DIM   1024
#define HEADS 16
#define HD    64
#define MTOT  (BDIM * NSEQ)          // 16384

// Scratch (static device arrays: no allocation at runtime)
__device__ float g_Q[(size_t)MTOT * DIM];
__device__ float g_K[(size_t)MTOT * DIM];
__device__ float g_V[(size_t)MTOT * DIM];
__device__ float g_attn[(size_t)MTOT * DIM];
__device__ float g_KV[BDIM * HEADS * HD * HD];   // [bh][d][v]
__device__ float g_Ksum[BDIM * HEADS * HD];      // [bh][d]

// ---- packed f32x2 helpers (2x fp32 FMA throughput on sm_103a) -------------
__device__ __forceinline__ unsigned long long pack2(float x) {
    unsigned long long r;
    unsigned u = __float_as_uint(x);
    asm("mov.b64 %0, {%1, %1};" : "=l"(r) : "r"(u));
    return r;
}
__device__ __forceinline__ void ffma2(unsigned long long& d,
                                      unsigned long long a,
                                      unsigned long long b) {
    asm("fma.rn.f32x2 %0, %1, %2, %0;" : "+l"(d) : "l"(a), "l"(b));
}

// ---------------------------------------------------------------------------
// GEMM: C[M,N] = act(A[M,K] @ W[N,K]^T + bias[N])
// Both A and W are K-major (row-major), so this is an "NT" product.
// 128x128 tile, BK=8, double-buffered smem, 8x8 per thread, f32x2 FMAs.
// ---------------------------------------------------------------------------
#define BM 128
#define BN 128
#define BK 8

__global__ __launch_bounds__(256, 2)
void gemm_nt_kernel(const float* __restrict__ A,
                    const float* __restrict__ W,
                    const float* __restrict__ bias,
                    float* __restrict__ C,
                    int M, int N, int K, int act)
{
    __shared__ __align__(16) float As[2][BK][BM + 4];
    __shared__ __align__(16) float Bs[2][BK][BN + 4];

    const int tid = threadIdx.x;
    const int tx = tid & 15;        // 0..15 -> output cols tx*8..tx*8+7
    const int ty = tid >> 4;        // 0..15 -> output rows ty*8..ty*8+7
    const int m0 = blockIdx.y * BM;
    const int n0 = blockIdx.x * BN;

    // cooperative load mapping: each thread loads one float4 of A and of W
    const int lrow = tid >> 1;           // 0..127
    const int lk   = (tid & 1) * 4;      // 0 or 4

    const float* Aptr = A + (size_t)(m0 + lrow) * K + lk;
    const float* Wptr = W + (size_t)(n0 + lrow) * K + lk;

    // stage 0
    float4 ra = *(const float4*)Aptr;
    float4 rb = *(const float4*)Wptr;
    As[0][lk + 0][lrow] = ra.x; As[0][lk + 1][lrow] = ra.y;
    As[0][lk + 2][lrow] = ra.z; As[0][lk + 3][lrow] = ra.w;
    Bs[0][lk + 0][lrow] = rb.x; Bs[0][lk + 1][lrow] = rb.y;
    Bs[0][lk + 2][lrow] = rb.z; Bs[0][lk + 3][lrow] = rb.w;
    __syncthreads();

    unsigned long long acc[8][4];
    #pragma unroll
    for (int i = 0; i < 8; i++)
        #pragma unroll
        for (int j = 0; j < 4; j++) acc[i][j] = 0ull;

    const int nstage = K / BK;
    int buf = 0;

    for (int s = 1; s <= nstage; s++) {
        float4 na, nb;
        const bool has_next = (s < nstage);
        if (has_next) {
            na = *(const float4*)(Aptr + s * BK);
            nb = *(const float4*)(Wptr + s * BK);
        }
        // compute current buffer
        #pragma unroll
        for (int kk = 0; kk < BK; kk++) {
            float a[8];
            *(float4*)&a[0] = *(const float4*)&As[buf][kk][ty * 8];
            *(float4*)&a[4] = *(const float4*)&As[buf][kk][ty * 8 + 4];
            unsigned long long bb[4];
            *(ulonglong2*)&bb[0] = *(const ulonglong2*)&Bs[buf][kk][tx * 8];
            *(ulonglong2*)&bb[2] = *(const ulonglong2*)&Bs[buf][kk][tx * 8 + 4];
            #pragma unroll
            for (int i = 0; i < 8; i++) {
                unsigned long long ap = pack2(a[i]);
                ffma2(acc[i][0], ap, bb[0]);
                ffma2(acc[i][1], ap, bb[1]);
                ffma2(acc[i][2], ap, bb[2]);
                ffma2(acc[i][3], ap, bb[3]);
            }
        }
        if (has_next) {
            const int nbuf = buf ^ 1;
            As[nbuf][lk + 0][lrow] = na.x; As[nbuf][lk + 1][lrow] = na.y;
            As[nbuf][lk + 2][lrow] = na.z; As[nbuf][lk + 3][lrow] = na.w;
            Bs[nbuf][lk + 0][lrow] = nb.x; Bs[nbuf][lk + 1][lrow] = nb.y;
            Bs[nbuf][lk + 2][lrow] = nb.z; Bs[nbuf][lk + 3][lrow] = nb.w;
            __syncthreads();
            buf = nbuf;
        }
    }

    // epilogue
    #pragma unroll
    for (int i = 0; i < 8; i++) {
        const int row = m0 + ty * 8 + i;
        float* Crow = C + (size_t)row * N + n0 + tx * 8;
        #pragma unroll
        for (int j = 0; j < 4; j++) {
            const int col = n0 + tx * 8 + j * 2;
            float lo = __uint_as_float((unsigned)(acc[i][j] & 0xffffffffull));
            float hi = __uint_as_float((unsigned)(acc[i][j] >> 32));
            lo += bias[col];
            hi += bias[col + 1];
            if (act) {  // elu(x)+1  ->  x>0 ? x+1 : exp(x)
                lo = (lo > 0.f) ? lo + 1.f : __expf(lo) ;
                hi = (hi > 0.f) ? hi + 1.f : __expf(hi) ;
                // __expf max rel err ~2^-22 in this range; exact enough,
                // but use expf for safety margin on the lo!=hi path:
            }
            float2 st; st.x = lo; st.y = hi;
            *(float2*)(Crow + j * 2) = st;
        }
    }
}

// ---------------------------------------------------------------------------
// zero KV / Ksum scratch
// ---------------------------------------------------------------------------
__global__ void zero_kv_kernel()
{
    const int i = blockIdx.x * 256 + threadIdx.x;
    if (i < BDIM * HEADS * HD * HD) g_KV[i] = 0.f;
    if (i < BDIM * HEADS * HD)      g_Ksum[i] = 0.f;
}

// ---------------------------------------------------------------------------
// KV[b,h,d,v] = sum_n K[b,n,h,d] * V[b,n,h,v];  Ksum[b,h,d] = sum_n K
// grid: (64 bh, 8 n-segments), 256 threads. atomicAdd reduction.
// ---------------------------------------------------------------------------
__global__ __launch_bounds__(256)
void kv_kernel(const float* __restrict__ K, const float* __restrict__ V)
{
    const int bh = blockIdx.x;
    const int seg = blockIdx.y;
    const int b = bh >> 4, h = bh & 15;
    const int tid = threadIdx.x;

    __shared__ __align__(16) float ks[8][64];
    __shared__ __align__(16) float vs[8][64];

    const int dq = tid >> 4;    // 0..15 -> d block dq*4
    const int vq = tid & 15;    // 0..15 -> v block vq*4
    float acc[4][4];
    #pragma unroll
    for (int a = 0; a < 4; a++)
        #pragma unroll
        for (int c = 0; c < 4; c++) acc[a][c] = 0.f;
    float ksacc = 0.f;

    const size_t base = ((size_t)b * NSEQ) * DIM + h * HD;
    const int row8 = tid >> 5;          // 0..7
    const int q = tid & 31;
    const bool isV = (q >= 16);
    const int c4 = (q & 15) * 4;

    const int nbeg = seg * (NSEQ / 8);
    const int nend = nbeg + (NSEQ / 8);

    for (int n0 = nbeg; n0 < nend; n0 += 8) {
        const size_t g = base + (size_t)(n0 + row8) * DIM + c4;
        float4 val = isV ? *(const float4*)(V + g) : *(const float4*)(K + g);
        float* dst = isV ? &vs[row8][c4] : &ks[row8][c4];
        *(float4*)dst = val;
        __syncthreads();
        #pragma unroll
        for (int i = 0; i < 8; i++) {
            const float4 kv = *(const float4*)&ks[i][dq * 4];
            const float4 vv = *(const float4*)&vs[i][vq * 4];
            acc[0][0] += kv.x * vv.x; acc[0][1] += kv.x * vv.y;
            acc[0][2] += kv.x * vv.z; acc[0][3] += kv.x * vv.w;
            acc[1][0] += kv.y * vv.x; acc[1][1] += kv.y * vv.y;
            acc[1][2] += kv.y * vv.z; acc[1][3] += kv.y * vv.w;
            acc[2][0] += kv.z * vv.x; acc[2][1] += kv.z * vv.y;
            acc[2][2] += kv.z * vv.z; acc[2][3] += kv.z * vv.w;
            acc[3][0] += kv.w * vv.x; acc[3][1] += kv.w * vv.y;
            acc[3][2] += kv.w * vv.z; acc[3][3] += kv.w * vv.w;
        }
        if (tid < 64) {
            #pragma unroll
            for (int i = 0; i < 8; i++) ksacc += ks[i][tid];
        }
        __syncthreads();
    }

    float* kvout = g_KV + bh * (HD * HD);
    #pragma unroll
    for (int a = 0; a < 4; a++)
        #pragma unroll
        for (int c = 0; c < 4; c++)
            atomicAdd(&kvout[(dq * 4 + a) * HD + vq * 4 + c], acc[a][c]);
    if (tid < 64) atomicAdd(&g_Ksum[bh * HD + tid], ksacc);
}

// ---------------------------------------------------------------------------
// attn[b,n,h,v] = (sum_d Q[b,n,h,d]*KV[bh,d,v]) /
//                 (sum_d Q[b,n,h,d]*Ksum[bh,d] + 1e-6) * sigmoid(stdp[h])
// grid: (64 n-tiles of 64, 64 bh), 256 threads
// ---------------------------------------------------------------------------
__global__ __launch_bounds__(256)
void attn_kernel(const float* __restrict__ Q,
                 const float* __restrict__ stdp,
                 float* __restrict__ out)
{
    const int bh = blockIdx.y;
    const int b = bh >> 4, h = bh & 15;
    const int n0 = blockIdx.x * 64;
    const int tid = threadIdx.x;

    __shared__ __align__(16) float qs[64][68];
    __shared__ __align__(16) float kvs[64][68];
    __shared__ float ksum_s[64];

    const size_t qbase = ((size_t)b * NSEQ + n0) * DIM + h * HD;
    #pragma unroll
    for (int i = 0; i < 4; i++) {
        const int slot = tid + i * 256;       // 0..1023
        const int r = slot >> 4;              // 0..63
        const int c4 = (slot & 15) * 4;       // 0..60
        *(float4*)&qs[r][c4]  = *(const float4*)(Q + qbase + (size_t)r * DIM + c4);
        *(float4*)&kvs[r][c4] = *(const float4*)(g_KV + bh * (HD * HD) + r * HD + c4);
    }
    if (tid < 64) ksum_s[tid] = g_Ksum[bh * HD + tid];
    __syncthreads();

    const int r = tid >> 2;        // 0..63 (row within tile)
    const int quad = tid & 3;      // 0..3 -> cols quad*16..+15
    float acc[16];
    #pragma unroll
    for (int j = 0; j < 16; j++) acc[j] = 0.f;
    float den = 0.f;

    #pragma unroll 4
    for (int d = 0; d < 64; d++) {
        const float qv = qs[r][d];
        den += qv * ksum_s[d];
        const float4 k0 = *(const float4*)&kvs[d][quad * 16 + 0];
        const float4 k1 = *(const float4*)&kvs[d][quad * 16 + 4];
        const float4 k2 = *(const float4*)&kvs[d][quad * 16 + 8];
        const float4 k3 = *(const float4*)&kvs[d][quad * 16 + 12];
        acc[0]  += qv * k0.x; acc[1]  += qv * k0.y; acc[2]  += qv * k0.z; acc[3]  += qv * k0.w;
        acc[4]  += qv * k1.x; acc[5]  += qv * k1.y; acc[6]  += qv * k1.z; acc[7]  += qv * k1.w;
        acc[8]  += qv * k2.x; acc[9]  += qv * k2.y; acc[10] += qv * k2.z; acc[11] += qv * k2.w;
        acc[12] += qv * k3.x; acc[13] += qv * k3.y; acc[14] += qv * k3.z; acc[15] += qv * k3.w;
    }

    const float sig = 1.f / (1.f + expf(-stdp[h]));
    const float scale = sig / (den + 1e-6f);

    const size_t obase = ((size_t)b * NSEQ + n0 + r) * DIM + h * HD + quad * 16;
    #pragma unroll
    for (int j = 0; j < 4; j++) {
        float4 st;
        st.x = acc[j * 4 + 0] * scale;
        st.y = acc[j * 4 + 1] * scale;
        st.z = acc[j * 4 + 2] * scale;
        st.w = acc[j * 4 + 3] * scale;
        *(float4*)(out + obase + j * 4) = st;
    }
}

// ---------------------------------------------------------------------------
// tail: second tuple output = stop_gradient(stdp) (identity copy)
// ---------------------------------------------------------------------------
__global__ void tail_kernel(const float* __restrict__ stdp,
                            float* __restrict__ out, int extra)
{
    const int i = threadIdx.x + blockIdx.x * blockDim.x;
    if (i < extra) {
        out[(size_t)MTOT * DIM + i] = (i < HEADS) ? stdp[i] : 0.f;
    }
}

// ---------------------------------------------------------------------------
extern "C" void kernel_launch(void* const* d_in, const int* in_sizes, int n_in,
                              void* d_out, int out_size)
{
    const float* x    = (const float*)d_in[0];
    const float* Wq   = (const float*)d_in[1];
    const float* bq   = (const float*)d_in[2];
    const float* Wk   = (const float*)d_in[3];
    const float* bk   = (const float*)d_in[4];
    const float* Wv   = (const float*)d_in[5];
    const float* bv   = (const float*)d_in[6];
    const float* Wo   = (const float*)d_in[7];
    const float* bo   = (const float*)d_in[8];
    const float* stdp = (const float*)d_in[9];
    float* out = (float*)d_out;

    float *pQ, *pK, *pV, *pAttn;
    cudaGetSymbolAddress((void**)&pQ, g_Q);
    cudaGetSymbolAddress((void**)&pK, g_K);
    cudaGetSymbolAddress((void**)&pV, g_V);
    cudaGetSymbolAddress((void**)&pAttn, g_attn);

    dim3 gg(DIM / BN, MTOT / BM);   // (8, 128)

    gemm_nt_kernel<<<gg, 256>>>(x, Wq, bq, pQ, MTOT, DIM, DIM, 1);
    gemm_nt_kernel<<<gg, 256>>>(x, Wk, bk, pK, MTOT, DIM, DIM, 1);
    gemm_nt_kernel<<<gg, 256>>>(x, Wv, bv, pV, MTOT, DIM, DIM, 0);

    zero_kv_kernel<<<(BDIM * HEADS * HD * HD + 255) / 256, 256>>>();

    kv_kernel<<<dim3(BDIM * HEADS, 8), 256>>>(pK, pV);

    attn_kernel<<<dim3(NSEQ / 64, BDIM * HEADS), 256>>>(pQ, stdp, pAttn);

    gemm_nt_kernel<<<gg, 256>>>(pAttn, Wo, bo, out, MTOT, DIM, DIM, 0);

    const int extra = out_size - MTOT * DIM;
    if (extra > 0) {
        tail_kernel<<<(extra + 255) / 256, 256>>>(stdp, out, extra);
    }
}